// round 1
// baseline (speedup 1.0000x reference)
#include <cuda_runtime.h>
#include <cuda_bf16.h>
#include <math.h>

#define D 128
#define NE 8192
#define NT 8192
#define EPSF 1e-8f

// Scratch (device globals; no allocation allowed)
__device__ float g_C[D * D];        // C = W @ U_k, row-major [d][k]
__device__ float g_Ae[NE * D];      // enroll projections, row-major [n][k], 2*lam folded
__device__ float g_At[NT * D];      // test projections, row-major [m][k]
__device__ float g_h1[NE];
__device__ float g_h2[NT];

// ---------------------------------------------------------------------------
// C[d][k] = sum_i W[d][i] * U[i][k]
// grid: 128 blocks (d), 128 threads (k). U loads coalesced across k.
// ---------------------------------------------------------------------------
__global__ void build_C_kernel(const float* __restrict__ W,
                               const float* __restrict__ U) {
    int d = blockIdx.x;
    int k = threadIdx.x;
    float acc = 0.f;
#pragma unroll 8
    for (int i = 0; i < D; i++)
        acc += W[d * D + i] * U[i * D + k];
    g_C[d * D + k] = acc;
}

// ---------------------------------------------------------------------------
// Projection + quadratic form. One CTA (128 threads) per vector n:
//   v = (x_n - miu) / (||x_n - miu|| + eps)
//   y = C^T v
//   h = y^T Q_hat y   (computed via Q^T, identical for the quadratic form)
//   store Y[n][k] = (which==0 ? 2*lam[k]*y_k : y_k)
// ---------------------------------------------------------------------------
__global__ void project_kernel(const float* __restrict__ X,
                               const float* __restrict__ miu,
                               const float* __restrict__ Q,
                               const float* __restrict__ lam,
                               int which) {
    __shared__ float v[D];
    __shared__ float y[D];
    __shared__ float red[4];

    int n = blockIdx.x;
    int t = threadIdx.x;
    int w = t >> 5;
    int lane = t & 31;

    float xv = X[n * D + t] - miu[t];

    // block reduce sum(xv*xv)
    float s = xv * xv;
#pragma unroll
    for (int o = 16; o > 0; o >>= 1)
        s += __shfl_xor_sync(0xffffffffu, s, o);
    if (lane == 0) red[w] = s;
    __syncthreads();
    float tot = red[0] + red[1] + red[2] + red[3];
    v[t] = xv / (sqrtf(tot) + EPSF);
    __syncthreads();

    // y_k = sum_d C[d][k] * v[d]   (coalesced across k)
    float acc = 0.f;
#pragma unroll 8
    for (int d = 0; d < D; d++)
        acc += g_C[d * D + t] * v[d];
    y[t] = acc;

    if (which == 0) {
        g_Ae[n * D + t] = 2.0f * lam[t] * acc;
    } else {
        g_At[n * D + t] = acc;
    }
    __syncthreads();

    // (Q^T y)_t  — coalesced across t; y^T Q^T y == y^T Q y
    float qy = 0.f;
#pragma unroll 8
    for (int j = 0; j < D; j++)
        qy += Q[j * D + t] * y[j];

    float c = acc * qy;
#pragma unroll
    for (int o = 16; o > 0; o >>= 1)
        c += __shfl_xor_sync(0xffffffffu, c, o);
    if (lane == 0) red[w] = c;
    __syncthreads();
    if (t == 0) {
        float h = red[0] + red[1] + red[2] + red[3];
        if (which == 0) g_h1[n] = h;
        else            g_h2[n] = h;
    }
}

// ---------------------------------------------------------------------------
// out[n][m] = sum_k Ae[n][k]*At[m][k] + h1[n] + h2[m]
// 128x128 tile per CTA, K=128 fully resident in smem (k-major, stride 129),
// 256 threads, 8x8 microtile each.
// ---------------------------------------------------------------------------
#define SMEM_STRIDE 129
#define GEMM_SMEM_BYTES (2 * 128 * SMEM_STRIDE * 4)

__global__ __launch_bounds__(256, 1)
void gemm_kernel(float* __restrict__ out) {
    extern __shared__ float sm[];
    float* As = sm;                      // As[k*129 + m]
    float* Bs = sm + 128 * SMEM_STRIDE;  // Bs[k*129 + n]

    int tid = threadIdx.x;
    int bm0 = blockIdx.y * 128;
    int bn0 = blockIdx.x * 128;

    const float4* A4 = (const float4*)(g_Ae + (size_t)bm0 * D);
    const float4* B4 = (const float4*)(g_At + (size_t)bn0 * D);

    // load tiles transposed into k-major smem
#pragma unroll
    for (int t = tid; t < 128 * 32; t += 256) {
        int row = t >> 5;
        int k4 = t & 31;
        int k = k4 * 4;
        float4 va = A4[row * 32 + k4];
        As[(k + 0) * SMEM_STRIDE + row] = va.x;
        As[(k + 1) * SMEM_STRIDE + row] = va.y;
        As[(k + 2) * SMEM_STRIDE + row] = va.z;
        As[(k + 3) * SMEM_STRIDE + row] = va.w;
        float4 vb = B4[row * 32 + k4];
        Bs[(k + 0) * SMEM_STRIDE + row] = vb.x;
        Bs[(k + 1) * SMEM_STRIDE + row] = vb.y;
        Bs[(k + 2) * SMEM_STRIDE + row] = vb.z;
        Bs[(k + 3) * SMEM_STRIDE + row] = vb.w;
    }
    __syncthreads();

    int tx = tid & 15;
    int ty = tid >> 4;
    int m0 = ty * 8;
    int n0 = tx * 8;

    float acc[8][8];
#pragma unroll
    for (int i = 0; i < 8; i++)
#pragma unroll
        for (int j = 0; j < 8; j++)
            acc[i][j] = 0.f;

#pragma unroll 8
    for (int k = 0; k < 128; k++) {
        float a[8], b[8];
#pragma unroll
        for (int i = 0; i < 8; i++) a[i] = As[k * SMEM_STRIDE + m0 + i];
#pragma unroll
        for (int j = 0; j < 8; j++) b[j] = Bs[k * SMEM_STRIDE + n0 + j];
#pragma unroll
        for (int i = 0; i < 8; i++)
#pragma unroll
            for (int j = 0; j < 8; j++)
                acc[i][j] = fmaf(a[i], b[j], acc[i][j]);
    }

    // epilogue: + h1[n] + h2[m], vectorized stores
    float hb[8];
#pragma unroll
    for (int j = 0; j < 8; j++) hb[j] = g_h2[bn0 + n0 + j];

#pragma unroll
    for (int i = 0; i < 8; i++) {
        int gm = bm0 + m0 + i;
        float ha = g_h1[gm];
        float4 r0, r1;
        r0.x = acc[i][0] + ha + hb[0];
        r0.y = acc[i][1] + ha + hb[1];
        r0.z = acc[i][2] + ha + hb[2];
        r0.w = acc[i][3] + ha + hb[3];
        r1.x = acc[i][4] + ha + hb[4];
        r1.y = acc[i][5] + ha + hb[5];
        r1.z = acc[i][6] + ha + hb[6];
        r1.w = acc[i][7] + ha + hb[7];
        float4* o4 = (float4*)(out + (size_t)gm * NT + bn0 + n0);
        o4[0] = r0;
        o4[1] = r1;
    }
}

// ---------------------------------------------------------------------------
extern "C" void kernel_launch(void* const* d_in, const int* in_sizes, int n_in,
                              void* d_out, int out_size) {
    const float* x_enroll = (const float*)d_in[0];
    const float* x_test   = (const float*)d_in[1];
    const float* W        = (const float*)d_in[2];
    const float* miu      = (const float*)d_in[3];
    const float* lam      = (const float*)d_in[4];
    const float* U_k      = (const float*)d_in[5];
    const float* Q_hat    = (const float*)d_in[6];
    float* out = (float*)d_out;

    build_C_kernel<<<D, D>>>(W, U_k);
    project_kernel<<<NE, D>>>(x_enroll, miu, Q_hat, lam, 0);
    project_kernel<<<NT, D>>>(x_test,   miu, Q_hat, lam, 1);

    cudaFuncSetAttribute(gemm_kernel,
                         cudaFuncAttributeMaxDynamicSharedMemorySize,
                         GEMM_SMEM_BYTES);
    dim3 grid(NT / 128, NE / 128);
    gemm_kernel<<<grid, 256, GEMM_SMEM_BYTES>>>(out);
}

// round 4
// speedup vs baseline: 2.5778x; 2.5778x over previous
#include <cuda_runtime.h>
#include <cuda_fp16.h>
#include <math.h>
#include <stdint.h>

#define D 128
#define NE 8192
#define NT 8192
#define EPSF 1e-8f
#define RPB 16

#define KT 256              // K after hi|lo concat
#define LDS_STRIDE 264      // padded smem row stride (elements)

// ---------------------------------------------------------------------------
// Device globals (no allocation allowed)
// ---------------------------------------------------------------------------
__device__ float g_C[D * D];
__device__ float g_h1[NE];
__device__ float g_h2[NT];
// row-major [n][256] fp16: cols 0-127 = hi, 128-255 = lo
__device__ __align__(16) __half g_Ae[NE * KT];
__device__ __align__(16) __half g_At[NT * KT];

// ---------------------------------------------------------------------------
__device__ __forceinline__ uint32_t smem_u32(const void* p) {
    uint32_t a;
    asm("{ .reg .u64 t; cvta.to.shared.u64 t, %1; cvt.u32.u64 %0, t; }"
        : "=r"(a) : "l"(p));
    return a;
}

__device__ __forceinline__ void cp_async16(uint32_t sdst, const void* gsrc) {
    asm volatile("cp.async.cg.shared.global [%0], [%1], 16;"
                 :: "r"(sdst), "l"(gsrc) : "memory");
}

#define CP_COMMIT() asm volatile("cp.async.commit_group;" ::: "memory")

__device__ __forceinline__ void ldsm_x4(uint32_t (&r)[4], uint32_t addr) {
    asm volatile("ldmatrix.sync.aligned.m8n8.x4.shared.b16 {%0,%1,%2,%3}, [%4];"
                 : "=r"(r[0]), "=r"(r[1]), "=r"(r[2]), "=r"(r[3]) : "r"(addr));
}

__device__ __forceinline__ void mma16816(float (&d)[4], const uint32_t (&a)[4],
                                         uint32_t b0, uint32_t b1) {
    asm volatile(
        "mma.sync.aligned.m16n8k16.row.col.f32.f16.f16.f32 "
        "{%0,%1,%2,%3}, {%4,%5,%6,%7}, {%8,%9}, {%0,%1,%2,%3};"
        : "+f"(d[0]), "+f"(d[1]), "+f"(d[2]), "+f"(d[3])
        : "r"(a[0]), "r"(a[1]), "r"(a[2]), "r"(a[3]), "r"(b0), "r"(b1));
}

// ---------------------------------------------------------------------------
// C = W @ U_k
// ---------------------------------------------------------------------------
__global__ void build_C_kernel(const float* __restrict__ W,
                               const float* __restrict__ U) {
    int d = blockIdx.x, k = threadIdx.x;
    float acc = 0.f;
#pragma unroll 8
    for (int i = 0; i < D; i++)
        acc += W[d * D + i] * U[i * D + k];
    g_C[d * D + k] = acc;
}

// ---------------------------------------------------------------------------
// Projection: 16 rows per 128-thread CTA.
//   v = (x-miu)/(||x-miu||+eps);  y = C^T v;  h = y^T Q y
//   stores fp16 hi/lo of (2*lam*y enroll / y test) row-major [n][256].
// ---------------------------------------------------------------------------
__global__ __launch_bounds__(128)
void project_kernel(const float* __restrict__ X,
                    const float* __restrict__ miu,
                    const float* __restrict__ Q,
                    const float* __restrict__ lam,
                    int which) {
    __shared__ float v[RPB][128];
    __shared__ float ys[RPB][128];
    __shared__ float red[RPB][4];

    int t = threadIdx.x, w = t >> 5, lane = t & 31;
    int n0 = blockIdx.x * RPB;
    float mu = miu[t];

    float xr[RPB];
#pragma unroll
    for (int i = 0; i < RPB; i++)
        xr[i] = X[(size_t)(n0 + i) * D + t] - mu;

#pragma unroll
    for (int i = 0; i < RPB; i++) {
        float s = xr[i] * xr[i];
#pragma unroll
        for (int o = 16; o > 0; o >>= 1) s += __shfl_xor_sync(0xffffffffu, s, o);
        if (lane == 0) red[i][w] = s;
    }
    __syncthreads();
#pragma unroll
    for (int i = 0; i < RPB; i++) {
        float tot = red[i][0] + red[i][1] + red[i][2] + red[i][3];
        v[i][t] = xr[i] / (sqrtf(tot) + EPSF);
    }
    __syncthreads();

    float acc[RPB];
#pragma unroll
    for (int i = 0; i < RPB; i++) acc[i] = 0.f;
#pragma unroll 4
    for (int d = 0; d < D; d++) {
        float c = g_C[d * D + t];
#pragma unroll
        for (int i = 0; i < RPB; i++) acc[i] = fmaf(c, v[i][d], acc[i]);
    }
#pragma unroll
    for (int i = 0; i < RPB; i++) ys[i][t] = acc[i];
    __syncthreads();

    float qacc[RPB];
#pragma unroll
    for (int i = 0; i < RPB; i++) qacc[i] = 0.f;
#pragma unroll 4
    for (int j = 0; j < D; j++) {
        float q = Q[j * D + t];
#pragma unroll
        for (int i = 0; i < RPB; i++) qacc[i] = fmaf(q, ys[i][j], qacc[i]);
    }
#pragma unroll
    for (int i = 0; i < RPB; i++) {
        float p = acc[i] * qacc[i];
#pragma unroll
        for (int o = 16; o > 0; o >>= 1) p += __shfl_xor_sync(0xffffffffu, p, o);
        if (lane == 0) red[i][w] = p;
    }
    __syncthreads();
    if (t < RPB) {
        float h = red[t][0] + red[t][1] + red[t][2] + red[t][3];
        if (which == 0) g_h1[n0 + t] = h;
        else            g_h2[n0 + t] = h;
    }

    // pack fp16 hi/lo row-major
    __half* dst = (which == 0) ? g_Ae : g_At;
    float f = (which == 0) ? 2.f * lam[t] : 1.f;
#pragma unroll
    for (int i = 0; i < RPB; i++) {
        float val = ys[i][t] * f;
        __half hi = __float2half_rn(val);
        __half lo = __float2half_rn(val - __half2float(hi));
        size_t base = (size_t)(n0 + i) * KT;
        dst[base + t] = hi;
        dst[base + 128 + t] = lo;
    }
}

// ---------------------------------------------------------------------------
// HMMA GEMM: 128x128 tile per CTA, 256 threads, 8 warps (2x4),
// K'=256 in smem, cp.async pipelined in 4 chunks of 64 K-columns.
// ---------------------------------------------------------------------------
#define GEMM_SMEM (2 * 128 * LDS_STRIDE * 2)   // 135168 bytes

__device__ __forceinline__ void mma_kstep(int k, uint32_t sA, uint32_t sB,
                                          int m0, int n0, int lane,
                                          float (&acc)[4][4][4]) {
    uint32_t a[4][4];
    int rowA = lane & 15;
    int koffA = k + ((lane >> 4) << 3);
#pragma unroll
    for (int mi = 0; mi < 4; mi++) {
        uint32_t ad = sA + (uint32_t)((m0 + mi * 16 + rowA) * LDS_STRIDE + koffA) * 2u;
        ldsm_x4(a[mi], ad);
    }
    uint32_t b[4][2];
    int nrow = ((lane >> 4) & 1) * 8 + (lane & 7);
    int koffB = k + ((lane >> 3) & 1) * 8;
#pragma unroll
    for (int j = 0; j < 2; j++) {
        uint32_t r[4];
        uint32_t bd = sB + (uint32_t)((n0 + j * 16 + nrow) * LDS_STRIDE + koffB) * 2u;
        ldsm_x4(r, bd);
        b[2 * j][0] = r[0]; b[2 * j][1] = r[1];
        b[2 * j + 1][0] = r[2]; b[2 * j + 1][1] = r[3];
    }
#pragma unroll
    for (int mi = 0; mi < 4; mi++)
#pragma unroll
        for (int nj = 0; nj < 4; nj++)
            mma16816(acc[mi][nj], a[mi], b[nj][0], b[nj][1]);
}

__global__ __launch_bounds__(256, 1)
void gemm_hmma(float* __restrict__ out) {
    extern __shared__ char sm[];
    uint32_t sA = smem_u32(sm);
    uint32_t sB = sA + 128 * LDS_STRIDE * 2;

    int tid = threadIdx.x;
    int lane = tid & 31, wid = tid >> 5;
    int bm0 = blockIdx.y * 128;
    int bn0 = blockIdx.x * 128;

    const char* gA = (const char*)(g_Ae + (size_t)bm0 * KT);
    const char* gB = (const char*)(g_At + (size_t)bn0 * KT);

    // issue 4 cp.async groups, each = 64 K-columns of both tiles
#pragma unroll
    for (int g = 0; g < 4; g++) {
#pragma unroll
        for (int u = 0; u < 8; u++) {
            int c = u * 256 + tid;           // 0..2047
            int tile = c >> 10;              // 0: A, 1: B
            int row = (c >> 3) & 127;
            int cc = c & 7;
            const char* gsrc = (tile ? gB : gA) + row * (KT * 2) + g * 128 + cc * 16;
            uint32_t sdst = (tile ? sB : sA) +
                            (uint32_t)(row * LDS_STRIDE * 2 + g * 128 + cc * 16);
            cp_async16(sdst, gsrc);
        }
        CP_COMMIT();
    }

    int m0 = (wid >> 2) * 64;
    int n0 = (wid & 3) * 32;

    float acc[4][4][4];
#pragma unroll
    for (int mi = 0; mi < 4; mi++)
#pragma unroll
        for (int nj = 0; nj < 4; nj++)
#pragma unroll
            for (int e = 0; e < 4; e++) acc[mi][nj][e] = 0.f;

#pragma unroll
    for (int chunk = 0; chunk < 4; chunk++) {
        if (chunk == 0)      asm volatile("cp.async.wait_group 3;" ::: "memory");
        else if (chunk == 1) asm volatile("cp.async.wait_group 2;" ::: "memory");
        else if (chunk == 2) asm volatile("cp.async.wait_group 1;" ::: "memory");
        else                 asm volatile("cp.async.wait_group 0;" ::: "memory");
        __syncthreads();
#pragma unroll
        for (int ks2 = 0; ks2 < 4; ks2++)
            mma_kstep(chunk * 64 + ks2 * 16, sA, sB, m0, n0, lane, acc);
    }

    // epilogue: + h1[row] + h2[col]
    int r0base = bm0 + m0 + (lane >> 2);
    int cbase = bn0 + n0 + 2 * (lane & 3);

    float h2v[4][2];
#pragma unroll
    for (int nj = 0; nj < 4; nj++) {
        h2v[nj][0] = g_h2[cbase + nj * 8];
        h2v[nj][1] = g_h2[cbase + nj * 8 + 1];
    }

#pragma unroll
    for (int mi = 0; mi < 4; mi++) {
        int gr0 = r0base + mi * 16;
        int gr1 = gr0 + 8;
        float h10 = g_h1[gr0];
        float h11 = g_h1[gr1];
#pragma unroll
        for (int nj = 0; nj < 4; nj++) {
            int gc = cbase + nj * 8;
            float2 v0 = make_float2(acc[mi][nj][0] + h10 + h2v[nj][0],
                                    acc[mi][nj][1] + h10 + h2v[nj][1]);
            float2 v1 = make_float2(acc[mi][nj][2] + h11 + h2v[nj][0],
                                    acc[mi][nj][3] + h11 + h2v[nj][1]);
            *(float2*)(out + (size_t)gr0 * NT + gc) = v0;
            *(float2*)(out + (size_t)gr1 * NT + gc) = v1;
        }
    }
}

// ---------------------------------------------------------------------------
extern "C" void kernel_launch(void* const* d_in, const int* in_sizes, int n_in,
                              void* d_out, int out_size) {
    const float* x_enroll = (const float*)d_in[0];
    const float* x_test   = (const float*)d_in[1];
    const float* W        = (const float*)d_in[2];
    const float* miu      = (const float*)d_in[3];
    const float* lam      = (const float*)d_in[4];
    const float* U_k      = (const float*)d_in[5];
    const float* Q_hat    = (const float*)d_in[6];
    float* out = (float*)d_out;

    build_C_kernel<<<D, D>>>(W, U_k);
    project_kernel<<<NE / RPB, 128>>>(x_enroll, miu, Q_hat, lam, 0);
    project_kernel<<<NT / RPB, 128>>>(x_test,   miu, Q_hat, lam, 1);

    cudaFuncSetAttribute(gemm_hmma, cudaFuncAttributeMaxDynamicSharedMemorySize,
                         GEMM_SMEM);
    dim3 grid(NT / 128, NE / 128);
    gemm_hmma<<<grid, 256, GEMM_SMEM>>>(out);
}

// round 5
// speedup vs baseline: 2.7088x; 1.0508x over previous
#include <cuda_runtime.h>
#include <cuda_fp16.h>
#include <math.h>
#include <stdint.h>

#define D 128
#define NE 8192
#define NT 8192
#define EPSF 1e-8f
#define RPB 16

#define KT 256              // K after hi|lo concat
#define LDS_STRIDE 264      // padded smem row stride (elements)

// ---------------------------------------------------------------------------
// Device globals (no allocation allowed)
// ---------------------------------------------------------------------------
__device__ float g_C[D * D];
__device__ float g_h1[NE];
__device__ float g_h2[NT];
// row-major [n][256] fp16: cols 0-127 = hi, 128-255 = lo
__device__ __align__(16) __half g_Ae[NE * KT];
__device__ __align__(16) __half g_At[NT * KT];

// ---------------------------------------------------------------------------
__device__ __forceinline__ uint32_t smem_u32(const void* p) {
    uint32_t a;
    asm("{ .reg .u64 t; cvta.to.shared.u64 t, %1; cvt.u32.u64 %0, t; }"
        : "=r"(a) : "l"(p));
    return a;
}

__device__ __forceinline__ void cp_async16(uint32_t sdst, const void* gsrc) {
    asm volatile("cp.async.cg.shared.global [%0], [%1], 16;"
                 :: "r"(sdst), "l"(gsrc) : "memory");
}

#define CP_COMMIT() asm volatile("cp.async.commit_group;" ::: "memory")

__device__ __forceinline__ void ldsm_x4(uint32_t (&r)[4], uint32_t addr) {
    asm volatile("ldmatrix.sync.aligned.m8n8.x4.shared.b16 {%0,%1,%2,%3}, [%4];"
                 : "=r"(r[0]), "=r"(r[1]), "=r"(r[2]), "=r"(r[3]) : "r"(addr));
}

__device__ __forceinline__ void mma16816(float (&d)[4], const uint32_t (&a)[4],
                                         uint32_t b0, uint32_t b1) {
    asm volatile(
        "mma.sync.aligned.m16n8k16.row.col.f32.f16.f16.f32 "
        "{%0,%1,%2,%3}, {%4,%5,%6,%7}, {%8,%9}, {%0,%1,%2,%3};"
        : "+f"(d[0]), "+f"(d[1]), "+f"(d[2]), "+f"(d[3])
        : "r"(a[0]), "r"(a[1]), "r"(a[2]), "r"(a[3]), "r"(b0), "r"(b1));
}

// ---------------------------------------------------------------------------
// C = W @ U_k
// ---------------------------------------------------------------------------
__global__ void build_C_kernel(const float* __restrict__ W,
                               const float* __restrict__ U) {
    int d = blockIdx.x, k = threadIdx.x;
    float acc = 0.f;
#pragma unroll 8
    for (int i = 0; i < D; i++)
        acc += W[d * D + i] * U[i * D + k];
    g_C[d * D + k] = acc;
}

// ---------------------------------------------------------------------------
// Merged projection: grid (NE/RPB, 2); y=0 enroll, y=1 test.
// 256 threads: lower 128 handle rows 0-7, upper 128 rows 8-15 of the block.
// ---------------------------------------------------------------------------
__global__ __launch_bounds__(256)
void project_kernel(const float* __restrict__ Xe,
                    const float* __restrict__ Xt,
                    const float* __restrict__ miu,
                    const float* __restrict__ Q,
                    const float* __restrict__ lam) {
    __shared__ float v[RPB][128];
    __shared__ float ys[RPB][128];
    __shared__ float red[RPB][4];

    int which = blockIdx.y;
    const float* X = which ? Xt : Xe;
    int t = threadIdx.x & 127;
    int rg = threadIdx.x >> 7;       // 0/1 -> rows [rg*8, rg*8+8)
    int r0 = rg * 8;
    int lane = threadIdx.x & 31;
    int w = (threadIdx.x >> 5) & 3;
    int n0 = blockIdx.x * RPB;
    float mu = miu[t];

    float xr[8];
#pragma unroll
    for (int i = 0; i < 8; i++)
        xr[i] = X[(size_t)(n0 + r0 + i) * D + t] - mu;

#pragma unroll
    for (int i = 0; i < 8; i++) {
        float s = xr[i] * xr[i];
#pragma unroll
        for (int o = 16; o > 0; o >>= 1) s += __shfl_xor_sync(0xffffffffu, s, o);
        if (lane == 0) red[r0 + i][w] = s;
    }
    __syncthreads();
#pragma unroll
    for (int i = 0; i < 8; i++) {
        float tot = red[r0 + i][0] + red[r0 + i][1] +
                    red[r0 + i][2] + red[r0 + i][3];
        v[r0 + i][t] = xr[i] / (sqrtf(tot) + EPSF);
    }
    __syncthreads();

    float acc[8];
#pragma unroll
    for (int i = 0; i < 8; i++) acc[i] = 0.f;
#pragma unroll 4
    for (int d = 0; d < D; d++) {
        float c = g_C[d * D + t];
#pragma unroll
        for (int i = 0; i < 8; i++) acc[i] = fmaf(c, v[r0 + i][d], acc[i]);
    }
#pragma unroll
    for (int i = 0; i < 8; i++) ys[r0 + i][t] = acc[i];
    __syncthreads();

    float qacc[8];
#pragma unroll
    for (int i = 0; i < 8; i++) qacc[i] = 0.f;
#pragma unroll 4
    for (int j = 0; j < D; j++) {
        float q = Q[j * D + t];
#pragma unroll
        for (int i = 0; i < 8; i++) qacc[i] = fmaf(q, ys[r0 + i][j], qacc[i]);
    }
#pragma unroll
    for (int i = 0; i < 8; i++) {
        float p = acc[i] * qacc[i];
#pragma unroll
        for (int o = 16; o > 0; o >>= 1) p += __shfl_xor_sync(0xffffffffu, p, o);
        if (lane == 0) red[r0 + i][w] = p;
    }
    __syncthreads();
    if (t < 8) {
        int row = r0 + t;
        float h = red[row][0] + red[row][1] + red[row][2] + red[row][3];
        if (which == 0) g_h1[n0 + row] = h;
        else            g_h2[n0 + row] = h;
    }

    // pack fp16 hi/lo row-major
    __half* dst = which ? g_At : g_Ae;
    float f = which ? 1.f : 2.f * lam[t];
#pragma unroll
    for (int i = 0; i < 8; i++) {
        float val = ys[r0 + i][t] * f;
        __half hi = __float2half_rn(val);
        __half lo = __float2half_rn(val - __half2float(hi));
        size_t base = (size_t)(n0 + r0 + i) * KT;
        dst[base + t] = hi;
        dst[base + 128 + t] = lo;
    }
}

// ---------------------------------------------------------------------------
// HMMA GEMM: 128(M) x 256(N) tile per CTA, 512 threads, 16 warps (2x8),
// K'=256 resident in smem, cp.async pipelined in 4 chunks of 64 K-columns.
// ---------------------------------------------------------------------------
#define GEMM_SMEM ((128 + 256) * LDS_STRIDE * 2)   // 202752 bytes

__device__ __forceinline__ void mma_kstep(int k, uint32_t sA, uint32_t sB,
                                          int m0, int n0, int lane,
                                          float (&acc)[4][4][4]) {
    uint32_t a[4][4];
    int rowA = lane & 15;
    int koffA = k + ((lane >> 4) << 3);
#pragma unroll
    for (int mi = 0; mi < 4; mi++) {
        uint32_t ad = sA + (uint32_t)((m0 + mi * 16 + rowA) * LDS_STRIDE + koffA) * 2u;
        ldsm_x4(a[mi], ad);
    }
    uint32_t b[4][2];
    int nrow = ((lane >> 4) & 1) * 8 + (lane & 7);
    int koffB = k + ((lane >> 3) & 1) * 8;
#pragma unroll
    for (int j = 0; j < 2; j++) {
        uint32_t r[4];
        uint32_t bd = sB + (uint32_t)((n0 + j * 16 + nrow) * LDS_STRIDE + koffB) * 2u;
        ldsm_x4(r, bd);
        b[2 * j][0] = r[0]; b[2 * j][1] = r[1];
        b[2 * j + 1][0] = r[2]; b[2 * j + 1][1] = r[3];
    }
#pragma unroll
    for (int mi = 0; mi < 4; mi++)
#pragma unroll
        for (int nj = 0; nj < 4; nj++)
            mma16816(acc[mi][nj], a[mi], b[nj][0], b[nj][1]);
}

__global__ __launch_bounds__(512, 1)
void gemm_hmma(float* __restrict__ out) {
    extern __shared__ char sm[];
    uint32_t sA = smem_u32(sm);
    uint32_t sB = sA + 128 * LDS_STRIDE * 2;

    int tid = threadIdx.x;
    int lane = tid & 31, wid = tid >> 5;
    int bm0 = blockIdx.y * 128;
    int bn0 = blockIdx.x * 256;

    const char* gA = (const char*)(g_Ae + (size_t)bm0 * KT);
    const char* gB = (const char*)(g_At + (size_t)bn0 * KT);

    // 4 cp.async groups, each = 64 K-columns of A (128 rows) + B (256 rows)
#pragma unroll
    for (int g = 0; g < 4; g++) {
#pragma unroll
        for (int u = 0; u < 6; u++) {
            int c = u * 512 + tid;           // 0..3071
            if (c < 1024) {
                int row = c >> 3, cc = c & 7;
                const char* gsrc = gA + row * (KT * 2) + g * 128 + cc * 16;
                uint32_t sdst = sA + (uint32_t)(row * LDS_STRIDE * 2 + g * 128 + cc * 16);
                cp_async16(sdst, gsrc);
            } else {
                int c2 = c - 1024;
                int row = c2 >> 3, cc = c2 & 7;
                const char* gsrc = gB + row * (KT * 2) + g * 128 + cc * 16;
                uint32_t sdst = sB + (uint32_t)(row * LDS_STRIDE * 2 + g * 128 + cc * 16);
                cp_async16(sdst, gsrc);
            }
        }
        CP_COMMIT();
    }

    int m0 = (wid >> 3) * 64;      // 2 m-groups
    int n0 = (wid & 7) * 32;       // 8 n-groups

    float acc[4][4][4];
#pragma unroll
    for (int mi = 0; mi < 4; mi++)
#pragma unroll
        for (int nj = 0; nj < 4; nj++)
#pragma unroll
            for (int e = 0; e < 4; e++) acc[mi][nj][e] = 0.f;

#pragma unroll
    for (int chunk = 0; chunk < 4; chunk++) {
        if (chunk == 0)      asm volatile("cp.async.wait_group 3;" ::: "memory");
        else if (chunk == 1) asm volatile("cp.async.wait_group 2;" ::: "memory");
        else if (chunk == 2) asm volatile("cp.async.wait_group 1;" ::: "memory");
        else                 asm volatile("cp.async.wait_group 0;" ::: "memory");
        __syncthreads();
#pragma unroll
        for (int ks2 = 0; ks2 < 4; ks2++)
            mma_kstep(chunk * 64 + ks2 * 16, sA, sB, m0, n0, lane, acc);
    }

    // epilogue: + h1[row] + h2[col]
    int r0base = bm0 + m0 + (lane >> 2);
    int cbase = bn0 + n0 + 2 * (lane & 3);

    float h2v[4][2];
#pragma unroll
    for (int nj = 0; nj < 4; nj++) {
        h2v[nj][0] = g_h2[cbase + nj * 8];
        h2v[nj][1] = g_h2[cbase + nj * 8 + 1];
    }

#pragma unroll
    for (int mi = 0; mi < 4; mi++) {
        int gr0 = r0base + mi * 16;
        int gr1 = gr0 + 8;
        float h10 = g_h1[gr0];
        float h11 = g_h1[gr1];
#pragma unroll
        for (int nj = 0; nj < 4; nj++) {
            int gc = cbase + nj * 8;
            float2 v0 = make_float2(acc[mi][nj][0] + h10 + h2v[nj][0],
                                    acc[mi][nj][1] + h10 + h2v[nj][1]);
            float2 v1 = make_float2(acc[mi][nj][2] + h11 + h2v[nj][0],
                                    acc[mi][nj][3] + h11 + h2v[nj][1]);
            *(float2*)(out + (size_t)gr0 * NT + gc) = v0;
            *(float2*)(out + (size_t)gr1 * NT + gc) = v1;
        }
    }
}

// ---------------------------------------------------------------------------
extern "C" void kernel_launch(void* const* d_in, const int* in_sizes, int n_in,
                              void* d_out, int out_size) {
    const float* x_enroll = (const float*)d_in[0];
    const float* x_test   = (const float*)d_in[1];
    const float* W        = (const float*)d_in[2];
    const float* miu      = (const float*)d_in[3];
    const float* lam      = (const float*)d_in[4];
    const float* U_k      = (const float*)d_in[5];
    const float* Q_hat    = (const float*)d_in[6];
    float* out = (float*)d_out;

    build_C_kernel<<<D, D>>>(W, U_k);
    project_kernel<<<dim3(NE / RPB, 2), 256>>>(x_enroll, x_test, miu, Q_hat, lam);

    cudaFuncSetAttribute(gemm_hmma, cudaFuncAttributeMaxDynamicSharedMemorySize,
                         GEMM_SMEM);
    dim3 grid(NT / 256, NE / 128);
    gemm_hmma<<<grid, 512, GEMM_SMEM>>>(out);
}

// round 6
// speedup vs baseline: 3.6544x; 1.3491x over previous
#include <cuda_runtime.h>
#include <cuda_fp16.h>
#include <math.h>
#include <stdint.h>

#define D 128
#define NE 8192
#define NT 8192
#define EPSF 1e-8f
#define RPB 16

#define KT 128              // plain fp16, K = 128
#define LDS_STRIDE 136      // padded smem row stride (elements)

// ---------------------------------------------------------------------------
// Device globals (no allocation allowed)
// ---------------------------------------------------------------------------
__device__ float g_C[D * D];
__device__ float g_h1[NE];
__device__ float g_h2[NT];
// row-major [n][128] fp16
__device__ __align__(16) __half g_Ae[NE * KT];
__device__ __align__(16) __half g_At[NT * KT];

// ---------------------------------------------------------------------------
__device__ __forceinline__ uint32_t smem_u32(const void* p) {
    uint32_t a;
    asm("{ .reg .u64 t; cvta.to.shared.u64 t, %1; cvt.u32.u64 %0, t; }"
        : "=r"(a) : "l"(p));
    return a;
}

__device__ __forceinline__ void cp_async16(uint32_t sdst, const void* gsrc) {
    asm volatile("cp.async.cg.shared.global [%0], [%1], 16;"
                 :: "r"(sdst), "l"(gsrc) : "memory");
}

#define CP_COMMIT() asm volatile("cp.async.commit_group;" ::: "memory")

__device__ __forceinline__ void ldsm_x4(uint32_t (&r)[4], uint32_t addr) {
    asm volatile("ldmatrix.sync.aligned.m8n8.x4.shared.b16 {%0,%1,%2,%3}, [%4];"
                 : "=r"(r[0]), "=r"(r[1]), "=r"(r[2]), "=r"(r[3]) : "r"(addr));
}

__device__ __forceinline__ void mma16816(float (&d)[4], const uint32_t (&a)[4],
                                         uint32_t b0, uint32_t b1) {
    asm volatile(
        "mma.sync.aligned.m16n8k16.row.col.f32.f16.f16.f32 "
        "{%0,%1,%2,%3}, {%4,%5,%6,%7}, {%8,%9}, {%0,%1,%2,%3};"
        : "+f"(d[0]), "+f"(d[1]), "+f"(d[2]), "+f"(d[3])
        : "r"(a[0]), "r"(a[1]), "r"(a[2]), "r"(a[3]), "r"(b0), "r"(b1));
}

// ---------------------------------------------------------------------------
// C = W @ U_k : 32 CTAs x 256 threads, U staged in smem (high-MLP load).
// CTA b computes rows [4b, 4b+4); thread (j = tid>>7) does rows 4b+2j, 4b+2j+1.
// ---------------------------------------------------------------------------
__global__ __launch_bounds__(256)
void build_C_kernel(const float* __restrict__ W,
                    const float* __restrict__ U) {
    __shared__ float Us[128 * 128];
    int tid = threadIdx.x;

    const float4* U4 = (const float4*)U;
    float4* Us4 = (float4*)Us;
#pragma unroll
    for (int i = 0; i < 16; i++)
        Us4[i * 256 + tid] = U4[i * 256 + tid];
    __syncthreads();

    int k = tid & 127;
    int d = blockIdx.x * 4 + (tid >> 7) * 2;
    float acc0 = 0.f, acc1 = 0.f;
#pragma unroll 16
    for (int i = 0; i < 128; i++) {
        float u = Us[i * 128 + k];
        acc0 = fmaf(W[d * 128 + i], u, acc0);
        acc1 = fmaf(W[(d + 1) * 128 + i], u, acc1);
    }
    g_C[d * 128 + k] = acc0;
    g_C[(d + 1) * 128 + k] = acc1;
}

// ---------------------------------------------------------------------------
// Merged projection: grid (NE/RPB, 2); y=0 enroll, y=1 test.
// 256 threads: lower 128 handle rows 0-7, upper 128 rows 8-15 of the block.
// ---------------------------------------------------------------------------
__global__ __launch_bounds__(256)
void project_kernel(const float* __restrict__ Xe,
                    const float* __restrict__ Xt,
                    const float* __restrict__ miu,
                    const float* __restrict__ Q,
                    const float* __restrict__ lam) {
    __shared__ float v[RPB][128];
    __shared__ float ys[RPB][128];
    __shared__ float red[RPB][4];

    int which = blockIdx.y;
    const float* X = which ? Xt : Xe;
    int t = threadIdx.x & 127;
    int rg = threadIdx.x >> 7;       // 0/1 -> rows [rg*8, rg*8+8)
    int r0 = rg * 8;
    int lane = threadIdx.x & 31;
    int w = (threadIdx.x >> 5) & 3;
    int n0 = blockIdx.x * RPB;
    float mu = miu[t];

    float xr[8];
#pragma unroll
    for (int i = 0; i < 8; i++)
        xr[i] = X[(size_t)(n0 + r0 + i) * D + t] - mu;

#pragma unroll
    for (int i = 0; i < 8; i++) {
        float s = xr[i] * xr[i];
#pragma unroll
        for (int o = 16; o > 0; o >>= 1) s += __shfl_xor_sync(0xffffffffu, s, o);
        if (lane == 0) red[r0 + i][w] = s;
    }
    __syncthreads();
#pragma unroll
    for (int i = 0; i < 8; i++) {
        float tot = red[r0 + i][0] + red[r0 + i][1] +
                    red[r0 + i][2] + red[r0 + i][3];
        v[r0 + i][t] = xr[i] / (sqrtf(tot) + EPSF);
    }
    __syncthreads();

    float acc[8];
#pragma unroll
    for (int i = 0; i < 8; i++) acc[i] = 0.f;
#pragma unroll 4
    for (int d = 0; d < D; d++) {
        float c = g_C[d * D + t];
#pragma unroll
        for (int i = 0; i < 8; i++) acc[i] = fmaf(c, v[r0 + i][d], acc[i]);
    }
#pragma unroll
    for (int i = 0; i < 8; i++) ys[r0 + i][t] = acc[i];
    __syncthreads();

    float qacc[8];
#pragma unroll
    for (int i = 0; i < 8; i++) qacc[i] = 0.f;
#pragma unroll 4
    for (int j = 0; j < D; j++) {
        float q = Q[j * D + t];
#pragma unroll
        for (int i = 0; i < 8; i++) qacc[i] = fmaf(q, ys[r0 + i][j], qacc[i]);
    }
#pragma unroll
    for (int i = 0; i < 8; i++) {
        float p = acc[i] * qacc[i];
#pragma unroll
        for (int o = 16; o > 0; o >>= 1) p += __shfl_xor_sync(0xffffffffu, p, o);
        if (lane == 0) red[r0 + i][w] = p;
    }
    __syncthreads();
    if (t < 8) {
        int row = r0 + t;
        float h = red[row][0] + red[row][1] + red[row][2] + red[row][3];
        if (which == 0) g_h1[n0 + row] = h;
        else            g_h2[n0 + row] = h;
    }

    // pack fp16 row-major
    __half* dst = which ? g_At : g_Ae;
    float f = which ? 1.f : 2.f * lam[t];
#pragma unroll
    for (int i = 0; i < 8; i++) {
        float val = ys[r0 + i][t] * f;
        dst[(size_t)(n0 + r0 + i) * KT + t] = __float2half_rn(val);
    }
}

// ---------------------------------------------------------------------------
// HMMA GEMM: 128(M) x 256(N) tile per CTA, 512 threads, 16 warps (2x8),
// K=128 resident in smem, cp.async pipelined in 2 chunks of 64 K-columns.
// ---------------------------------------------------------------------------
#define GEMM_SMEM ((128 + 256) * LDS_STRIDE * 2)   // 104448 bytes

__device__ __forceinline__ void mma_kstep(int k, uint32_t sA, uint32_t sB,
                                          int m0, int n0, int lane,
                                          float (&acc)[4][4][4]) {
    uint32_t a[4][4];
    int rowA = lane & 15;
    int koffA = k + ((lane >> 4) << 3);
#pragma unroll
    for (int mi = 0; mi < 4; mi++) {
        uint32_t ad = sA + (uint32_t)((m0 + mi * 16 + rowA) * LDS_STRIDE + koffA) * 2u;
        ldsm_x4(a[mi], ad);
    }
    uint32_t b[4][2];
    int nrow = ((lane >> 4) & 1) * 8 + (lane & 7);
    int koffB = k + ((lane >> 3) & 1) * 8;
#pragma unroll
    for (int j = 0; j < 2; j++) {
        uint32_t r[4];
        uint32_t bd = sB + (uint32_t)((n0 + j * 16 + nrow) * LDS_STRIDE + koffB) * 2u;
        ldsm_x4(r, bd);
        b[2 * j][0] = r[0]; b[2 * j][1] = r[1];
        b[2 * j + 1][0] = r[2]; b[2 * j + 1][1] = r[3];
    }
#pragma unroll
    for (int mi = 0; mi < 4; mi++)
#pragma unroll
        for (int nj = 0; nj < 4; nj++)
            mma16816(acc[mi][nj], a[mi], b[nj][0], b[nj][1]);
}

__global__ __launch_bounds__(512, 1)
void gemm_hmma(float* __restrict__ out) {
    extern __shared__ char sm[];
    uint32_t sA = smem_u32(sm);
    uint32_t sB = sA + 128 * LDS_STRIDE * 2;

    int tid = threadIdx.x;
    int lane = tid & 31, wid = tid >> 5;
    int bm0 = blockIdx.y * 128;
    int bn0 = blockIdx.x * 256;

    const char* gA = (const char*)(g_Ae + (size_t)bm0 * KT);
    const char* gB = (const char*)(g_At + (size_t)bn0 * KT);

    // 2 cp.async groups, each = 64 K-columns (128 B/row) of A (128 rows) + B (256 rows)
#pragma unroll
    for (int g = 0; g < 2; g++) {
#pragma unroll
        for (int u = 0; u < 6; u++) {
            int c = u * 512 + tid;           // 0..3071
            if (c < 1024) {
                int row = c >> 3, cc = c & 7;
                const char* gsrc = gA + row * (KT * 2) + g * 128 + cc * 16;
                uint32_t sdst = sA + (uint32_t)(row * LDS_STRIDE * 2 + g * 128 + cc * 16);
                cp_async16(sdst, gsrc);
            } else {
                int c2 = c - 1024;
                int row = c2 >> 3, cc = c2 & 7;
                const char* gsrc = gB + row * (KT * 2) + g * 128 + cc * 16;
                uint32_t sdst = sB + (uint32_t)(row * LDS_STRIDE * 2 + g * 128 + cc * 16);
                cp_async16(sdst, gsrc);
            }
        }
        CP_COMMIT();
    }

    int m0 = (wid >> 3) * 64;      // 2 m-groups
    int n0 = (wid & 7) * 32;       // 8 n-groups

    float acc[4][4][4];
#pragma unroll
    for (int mi = 0; mi < 4; mi++)
#pragma unroll
        for (int nj = 0; nj < 4; nj++)
#pragma unroll
            for (int e = 0; e < 4; e++) acc[mi][nj][e] = 0.f;

    asm volatile("cp.async.wait_group 1;" ::: "memory");
    __syncthreads();
#pragma unroll
    for (int ks = 0; ks < 4; ks++)
        mma_kstep(ks * 16, sA, sB, m0, n0, lane, acc);

    asm volatile("cp.async.wait_group 0;" ::: "memory");
    __syncthreads();
#pragma unroll
    for (int ks = 4; ks < 8; ks++)
        mma_kstep(ks * 16, sA, sB, m0, n0, lane, acc);

    // epilogue: + h1[row] + h2[col]
    int r0base = bm0 + m0 + (lane >> 2);
    int cbase = bn0 + n0 + 2 * (lane & 3);

    float h2v[4][2];
#pragma unroll
    for (int nj = 0; nj < 4; nj++) {
        h2v[nj][0] = g_h2[cbase + nj * 8];
        h2v[nj][1] = g_h2[cbase + nj * 8 + 1];
    }

#pragma unroll
    for (int mi = 0; mi < 4; mi++) {
        int gr0 = r0base + mi * 16;
        int gr1 = gr0 + 8;
        float h10 = g_h1[gr0];
        float h11 = g_h1[gr1];
#pragma unroll
        for (int nj = 0; nj < 4; nj++) {
            int gc = cbase + nj * 8;
            float2 v0 = make_float2(acc[mi][nj][0] + h10 + h2v[nj][0],
                                    acc[mi][nj][1] + h10 + h2v[nj][1]);
            float2 v1 = make_float2(acc[mi][nj][2] + h11 + h2v[nj][0],
                                    acc[mi][nj][3] + h11 + h2v[nj][1]);
            *(float2*)(out + (size_t)gr0 * NT + gc) = v0;
            *(float2*)(out + (size_t)gr1 * NT + gc) = v1;
        }
    }
}

// ---------------------------------------------------------------------------
extern "C" void kernel_launch(void* const* d_in, const int* in_sizes, int n_in,
                              void* d_out, int out_size) {
    const float* x_enroll = (const float*)d_in[0];
    const float* x_test   = (const float*)d_in[1];
    const float* W        = (const float*)d_in[2];
    const float* miu      = (const float*)d_in[3];
    const float* lam      = (const float*)d_in[4];
    const float* U_k      = (const float*)d_in[5];
    const float* Q_hat    = (const float*)d_in[6];
    float* out = (float*)d_out;

    build_C_kernel<<<32, 256>>>(W, U_k);
    project_kernel<<<dim3(NE / RPB, 2), 256>>>(x_enroll, x_test, miu, Q_hat, lam);

    cudaFuncSetAttribute(gemm_hmma, cudaFuncAttributeMaxDynamicSharedMemorySize,
                         GEMM_SMEM);
    dim3 grid(NT / 256, NE / 128);
    gemm_hmma<<<grid, 512, GEMM_SMEM>>>(out);
}

// round 7
// speedup vs baseline: 3.9476x; 1.0802x over previous
#include <cuda_runtime.h>
#include <cuda_fp16.h>
#include <math.h>
#include <stdint.h>

#define D 128
#define NE 8192
#define NT 8192
#define EPSF 1e-8f
#define RPB 16

#define KT 128              // fp16 K
#define LDS_STRIDE 136      // padded smem row stride (elements)

// ---------------------------------------------------------------------------
// Device globals (no allocation allowed)
// ---------------------------------------------------------------------------
__device__ float g_C[D * D];
__device__ float g_h1[NE];
__device__ float g_h2[NT];
__device__ __align__(16) __half g_Ae[NE * KT];
__device__ __align__(16) __half g_At[NT * KT];

// ---------------------------------------------------------------------------
__device__ __forceinline__ uint32_t smem_u32(const void* p) {
    uint32_t a;
    asm("{ .reg .u64 t; cvta.to.shared.u64 t, %1; cvt.u32.u64 %0, t; }"
        : "=r"(a) : "l"(p));
    return a;
}

__device__ __forceinline__ void cp_async16(uint32_t sdst, const void* gsrc) {
    asm volatile("cp.async.cg.shared.global [%0], [%1], 16;"
                 :: "r"(sdst), "l"(gsrc) : "memory");
}

#define CP_COMMIT() asm volatile("cp.async.commit_group;" ::: "memory")

__device__ __forceinline__ void ldsm_x4(uint32_t (&r)[4], uint32_t addr) {
    asm volatile("ldmatrix.sync.aligned.m8n8.x4.shared.b16 {%0,%1,%2,%3}, [%4];"
                 : "=r"(r[0]), "=r"(r[1]), "=r"(r[2]), "=r"(r[3]) : "r"(addr));
}

__device__ __forceinline__ void mma16816(float (&d)[4], const uint32_t (&a)[4],
                                         uint32_t b0, uint32_t b1) {
    asm volatile(
        "mma.sync.aligned.m16n8k16.row.col.f32.f16.f16.f32 "
        "{%0,%1,%2,%3}, {%4,%5,%6,%7}, {%8,%9}, {%0,%1,%2,%3};"
        : "+f"(d[0]), "+f"(d[1]), "+f"(d[2]), "+f"(d[3])
        : "r"(a[0]), "r"(a[1]), "r"(a[2]), "r"(a[3]), "r"(b0), "r"(b1));
}

// ---------------------------------------------------------------------------
// C = W @ U_k : 32 CTAs x 256 threads, U staged in smem.
// ---------------------------------------------------------------------------
__global__ __launch_bounds__(256)
void build_C_kernel(const float* __restrict__ W,
                    const float* __restrict__ U) {
    __shared__ float Us[128 * 128];
    int tid = threadIdx.x;

    const float4* U4 = (const float4*)U;
    float4* Us4 = (float4*)Us;
#pragma unroll
    for (int i = 0; i < 16; i++)
        Us4[i * 256 + tid] = U4[i * 256 + tid];
    __syncthreads();

    int k = tid & 127;
    int d = blockIdx.x * 4 + (tid >> 7) * 2;
    float acc0 = 0.f, acc1 = 0.f;
#pragma unroll 16
    for (int i = 0; i < 128; i++) {
        float u = Us[i * 128 + k];
        acc0 = fmaf(W[d * 128 + i], u, acc0);
        acc1 = fmaf(W[(d + 1) * 128 + i], u, acc1);
    }
    g_C[d * 128 + k] = acc0;
    g_C[(d + 1) * 128 + k] = acc1;
}

// ---------------------------------------------------------------------------
// Merged projection: grid (NE/RPB, 2); y=0 enroll, y=1 test.
// 256 threads: lower 128 handle rows 0-7, upper 128 rows 8-15.
// Matvec phases use LDS.128 broadcast reads (4x fewer shared loads).
// ---------------------------------------------------------------------------
__global__ __launch_bounds__(256)
void project_kernel(const float* __restrict__ Xe,
                    const float* __restrict__ Xt,
                    const float* __restrict__ miu,
                    const float* __restrict__ Q,
                    const float* __restrict__ lam) {
    __shared__ __align__(16) float v[RPB][128];
    __shared__ __align__(16) float ys[RPB][128];
    __shared__ float red[RPB][4];

    int which = blockIdx.y;
    const float* X = which ? Xt : Xe;
    int t = threadIdx.x & 127;
    int rg = threadIdx.x >> 7;
    int r0 = rg * 8;
    int lane = threadIdx.x & 31;
    int w = (threadIdx.x >> 5) & 3;
    int n0 = blockIdx.x * RPB;
    float mu = miu[t];

    float xr[8];
#pragma unroll
    for (int i = 0; i < 8; i++)
        xr[i] = X[(size_t)(n0 + r0 + i) * D + t] - mu;

#pragma unroll
    for (int i = 0; i < 8; i++) {
        float s = xr[i] * xr[i];
#pragma unroll
        for (int o = 16; o > 0; o >>= 1) s += __shfl_xor_sync(0xffffffffu, s, o);
        if (lane == 0) red[r0 + i][w] = s;
    }
    __syncthreads();
#pragma unroll
    for (int i = 0; i < 8; i++) {
        float tot = red[r0 + i][0] + red[r0 + i][1] +
                    red[r0 + i][2] + red[r0 + i][3];
        v[r0 + i][t] = xr[i] / (sqrtf(tot) + EPSF);
    }
    __syncthreads();

    float acc[8];
#pragma unroll
    for (int i = 0; i < 8; i++) acc[i] = 0.f;
#pragma unroll 4
    for (int d = 0; d < D; d += 4) {
        float c0 = g_C[(d + 0) * D + t];
        float c1 = g_C[(d + 1) * D + t];
        float c2 = g_C[(d + 2) * D + t];
        float c3 = g_C[(d + 3) * D + t];
#pragma unroll
        for (int i = 0; i < 8; i++) {
            float4 vv = *(const float4*)&v[r0 + i][d];
            acc[i] = fmaf(c0, vv.x, acc[i]);
            acc[i] = fmaf(c1, vv.y, acc[i]);
            acc[i] = fmaf(c2, vv.z, acc[i]);
            acc[i] = fmaf(c3, vv.w, acc[i]);
        }
    }
#pragma unroll
    for (int i = 0; i < 8; i++) ys[r0 + i][t] = acc[i];
    __syncthreads();

    float qacc[8];
#pragma unroll
    for (int i = 0; i < 8; i++) qacc[i] = 0.f;
#pragma unroll 4
    for (int j = 0; j < D; j += 4) {
        float q0 = Q[(j + 0) * D + t];
        float q1 = Q[(j + 1) * D + t];
        float q2 = Q[(j + 2) * D + t];
        float q3 = Q[(j + 3) * D + t];
#pragma unroll
        for (int i = 0; i < 8; i++) {
            float4 yy = *(const float4*)&ys[r0 + i][j];
            qacc[i] = fmaf(q0, yy.x, qacc[i]);
            qacc[i] = fmaf(q1, yy.y, qacc[i]);
            qacc[i] = fmaf(q2, yy.z, qacc[i]);
            qacc[i] = fmaf(q3, yy.w, qacc[i]);
        }
    }
#pragma unroll
    for (int i = 0; i < 8; i++) {
        float p = acc[i] * qacc[i];
#pragma unroll
        for (int o = 16; o > 0; o >>= 1) p += __shfl_xor_sync(0xffffffffu, p, o);
        if (lane == 0) red[r0 + i][w] = p;
    }
    __syncthreads();
    if (t < 8) {
        int row = r0 + t;
        float h = red[row][0] + red[row][1] + red[row][2] + red[row][3];
        if (which == 0) g_h1[n0 + row] = h;
        else            g_h2[n0 + row] = h;
    }

    __half* dst = which ? g_At : g_Ae;
    float f = which ? 1.f : 2.f * lam[t];
#pragma unroll
    for (int i = 0; i < 8; i++) {
        float val = ys[r0 + i][t] * f;
        dst[(size_t)(n0 + r0 + i) * KT + t] = __float2half_rn(val);
    }
}

// ---------------------------------------------------------------------------
// HMMA GEMM: 128(M) x 128(N) tile per CTA, 256 threads, 8 warps (2x4),
// 2 CTAs/SM. K=128 in smem, cp.async pipelined in 2 chunks of 64 K-cols.
// ---------------------------------------------------------------------------
#define GEMM_SMEM (2 * 128 * LDS_STRIDE * 2)   // 69632 bytes

__device__ __forceinline__ void mma_kstep(int k, uint32_t sA, uint32_t sB,
                                          int m0, int n0, int lane,
                                          float (&acc)[4][4][4]) {
    uint32_t a[4][4];
    int rowA = lane & 15;
    int koffA = k + ((lane >> 4) << 3);
#pragma unroll
    for (int mi = 0; mi < 4; mi++) {
        uint32_t ad = sA + (uint32_t)((m0 + mi * 16 + rowA) * LDS_STRIDE + koffA) * 2u;
        ldsm_x4(a[mi], ad);
    }
    uint32_t b[4][2];
    int nrow = ((lane >> 4) & 1) * 8 + (lane & 7);
    int koffB = k + ((lane >> 3) & 1) * 8;
#pragma unroll
    for (int j = 0; j < 2; j++) {
        uint32_t r[4];
        uint32_t bd = sB + (uint32_t)((n0 + j * 16 + nrow) * LDS_STRIDE + koffB) * 2u;
        ldsm_x4(r, bd);
        b[2 * j][0] = r[0]; b[2 * j][1] = r[1];
        b[2 * j + 1][0] = r[2]; b[2 * j + 1][1] = r[3];
    }
#pragma unroll
    for (int mi = 0; mi < 4; mi++)
#pragma unroll
        for (int nj = 0; nj < 4; nj++)
            mma16816(acc[mi][nj], a[mi], b[nj][0], b[nj][1]);
}

__global__ __launch_bounds__(256, 2)
void gemm_hmma(float* __restrict__ out) {
    extern __shared__ char sm[];
    uint32_t sA = smem_u32(sm);
    uint32_t sB = sA + 128 * LDS_STRIDE * 2;

    int tid = threadIdx.x;
    int lane = tid & 31, wid = tid >> 5;
    int bm0 = blockIdx.y * 128;
    int bn0 = blockIdx.x * 128;

    const char* gA = (const char*)(g_Ae + (size_t)bm0 * KT);
    const char* gB = (const char*)(g_At + (size_t)bn0 * KT);

    // 2 cp.async groups, each = 64 K-columns (128 B/row) of A + B (128 rows each)
#pragma unroll
    for (int g = 0; g < 2; g++) {
#pragma unroll
        for (int u = 0; u < 8; u++) {
            int c = u * 256 + tid;           // 0..2047
            int tile = c >> 10;              // 0: A, 1: B
            int row = (c >> 3) & 127;
            int cc = c & 7;
            const char* gsrc = (tile ? gB : gA) + row * (KT * 2) + g * 128 + cc * 16;
            uint32_t sdst = (tile ? sB : sA) +
                            (uint32_t)(row * LDS_STRIDE * 2 + g * 128 + cc * 16);
            cp_async16(sdst, gsrc);
        }
        CP_COMMIT();
    }

    int m0 = (wid >> 2) * 64;      // 2 m-groups
    int n0 = (wid & 3) * 32;       // 4 n-groups

    float acc[4][4][4];
#pragma unroll
    for (int mi = 0; mi < 4; mi++)
#pragma unroll
        for (int nj = 0; nj < 4; nj++)
#pragma unroll
            for (int e = 0; e < 4; e++) acc[mi][nj][e] = 0.f;

    asm volatile("cp.async.wait_group 1;" ::: "memory");
    __syncthreads();
#pragma unroll
    for (int ks = 0; ks < 4; ks++)
        mma_kstep(ks * 16, sA, sB, m0, n0, lane, acc);

    asm volatile("cp.async.wait_group 0;" ::: "memory");
    __syncthreads();
#pragma unroll
    for (int ks = 4; ks < 8; ks++)
        mma_kstep(ks * 16, sA, sB, m0, n0, lane, acc);

    // epilogue: + h1[row] + h2[col]
    int r0base = bm0 + m0 + (lane >> 2);
    int cbase = bn0 + n0 + 2 * (lane & 3);

    float h2v[4][2];
#pragma unroll
    for (int nj = 0; nj < 4; nj++) {
        h2v[nj][0] = g_h2[cbase + nj * 8];
        h2v[nj][1] = g_h2[cbase + nj * 8 + 1];
    }

#pragma unroll
    for (int mi = 0; mi < 4; mi++) {
        int gr0 = r0base + mi * 16;
        int gr1 = gr0 + 8;
        float h10 = g_h1[gr0];
        float h11 = g_h1[gr1];
#pragma unroll
        for (int nj = 0; nj < 4; nj++) {
            int gc = cbase + nj * 8;
            float2 v0 = make_float2(acc[mi][nj][0] + h10 + h2v[nj][0],
                                    acc[mi][nj][1] + h10 + h2v[nj][1]);
            float2 v1 = make_float2(acc[mi][nj][2] + h11 + h2v[nj][0],
                                    acc[mi][nj][3] + h11 + h2v[nj][1]);
            *(float2*)(out + (size_t)gr0 * NT + gc) = v0;
            *(float2*)(out + (size_t)gr1 * NT + gc) = v1;
        }
    }
}

// ---------------------------------------------------------------------------
extern "C" void kernel_launch(void* const* d_in, const int* in_sizes, int n_in,
                              void* d_out, int out_size) {
    const float* x_enroll = (const float*)d_in[0];
    const float* x_test   = (const float*)d_in[1];
    const float* W        = (const float*)d_in[2];
    const float* miu      = (const float*)d_in[3];
    const float* lam      = (const float*)d_in[4];
    const float* U_k      = (const float*)d_in[5];
    const float* Q_hat    = (const float*)d_in[6];
    float* out = (float*)d_out;

    build_C_kernel<<<32, 256>>>(W, U_k);
    project_kernel<<<dim3(NE / RPB, 2), 256>>>(x_enroll, x_test, miu, Q_hat, lam);

    cudaFuncSetAttribute(gemm_hmma, cudaFuncAttributeMaxDynamicSharedMemorySize,
                         GEMM_SMEM);
    dim3 grid(NT / 128, NE / 128);
    gemm_hmma<<<grid, 256, GEMM_SMEM>>>(out);
}

// round 9
// speedup vs baseline: 3.9846x; 1.0094x over previous
#include <cuda_runtime.h>
#include <cuda_fp16.h>
#include <math.h>
#include <stdint.h>

#define D 128
#define NE 8192
#define NT 8192
#define EPSF 1e-8f
#define RPB 16

#define KT 128              // fp16 K
#define LDS_STRIDE 136      // padded smem row stride (elements)

// ---------------------------------------------------------------------------
// Device globals (no allocation allowed)
// ---------------------------------------------------------------------------
__device__ float g_C[D * D];
__device__ float g_h1[NE];
__device__ float g_h2[NT];
__device__ __align__(16) __half g_Ae[NE * KT];
__device__ __align__(16) __half g_At[NT * KT];

// ---------------------------------------------------------------------------
__device__ __forceinline__ uint32_t smem_u32(const void* p) {
    uint32_t a;
    asm("{ .reg .u64 t; cvta.to.shared.u64 t, %1; cvt.u32.u64 %0, t; }"
        : "=r"(a) : "l"(p));
    return a;
}

__device__ __forceinline__ void cp_async16(uint32_t sdst, const void* gsrc) {
    asm volatile("cp.async.cg.shared.global [%0], [%1], 16;"
                 :: "r"(sdst), "l"(gsrc) : "memory");
}

#define CP_COMMIT() asm volatile("cp.async.commit_group;" ::: "memory")

__device__ __forceinline__ void ldsm_x4(uint32_t (&r)[4], uint32_t addr) {
    asm volatile("ldmatrix.sync.aligned.m8n8.x4.shared.b16 {%0,%1,%2,%3}, [%4];"
                 : "=r"(r[0]), "=r"(r[1]), "=r"(r[2]), "=r"(r[3]) : "r"(addr));
}

__device__ __forceinline__ void mma16816(float (&d)[4], const uint32_t (&a)[4],
                                         uint32_t b0, uint32_t b1) {
    asm volatile(
        "mma.sync.aligned.m16n8k16.row.col.f32.f16.f16.f32 "
        "{%0,%1,%2,%3}, {%4,%5,%6,%7}, {%8,%9}, {%0,%1,%2,%3};"
        : "+f"(d[0]), "+f"(d[1]), "+f"(d[2]), "+f"(d[3])
        : "r"(a[0]), "r"(a[1]), "r"(a[2]), "r"(a[3]), "r"(b0), "r"(b1));
}

// ---------------------------------------------------------------------------
// C = W @ U_k : 128 CTAs x 128 threads, one C row per CTA.
// ---------------------------------------------------------------------------
__global__ __launch_bounds__(128)
void build_C_kernel(const float* __restrict__ W,
                    const float* __restrict__ U) {
    __shared__ float Wrow[128];
    int d = blockIdx.x;
    int k = threadIdx.x;
    Wrow[k] = W[d * 128 + k];
    __syncthreads();

    float acc = 0.f;
#pragma unroll 16
    for (int i = 0; i < 128; i++)
        acc = fmaf(Wrow[i], U[i * 128 + k], acc);
    g_C[d * 128 + k] = acc;
}

// ---------------------------------------------------------------------------
// Merged projection: grid (NE/RPB, 2); y=0 enroll, y=1 test.
// ---------------------------------------------------------------------------
__global__ __launch_bounds__(256)
void project_kernel(const float* __restrict__ Xe,
                    const float* __restrict__ Xt,
                    const float* __restrict__ miu,
                    const float* __restrict__ Q,
                    const float* __restrict__ lam) {
    __shared__ __align__(16) float v[RPB][128];
    __shared__ __align__(16) float ys[RPB][128];
    __shared__ float red[RPB][4];

    int which = blockIdx.y;
    const float* X = which ? Xt : Xe;
    int t = threadIdx.x & 127;
    int rg = threadIdx.x >> 7;
    int r0 = rg * 8;
    int lane = threadIdx.x & 31;
    int w = (threadIdx.x >> 5) & 3;
    int n0 = blockIdx.x * RPB;
    float mu = miu[t];

    float xr[8];
#pragma unroll
    for (int i = 0; i < 8; i++)
        xr[i] = X[(size_t)(n0 + r0 + i) * D + t] - mu;

#pragma unroll
    for (int i = 0; i < 8; i++) {
        float s = xr[i] * xr[i];
#pragma unroll
        for (int o = 16; o > 0; o >>= 1) s += __shfl_xor_sync(0xffffffffu, s, o);
        if (lane == 0) red[r0 + i][w] = s;
    }
    __syncthreads();
#pragma unroll
    for (int i = 0; i < 8; i++) {
        float tot = red[r0 + i][0] + red[r0 + i][1] +
                    red[r0 + i][2] + red[r0 + i][3];
        v[r0 + i][t] = xr[i] / (sqrtf(tot) + EPSF);
    }
    __syncthreads();

    float acc[8];
#pragma unroll
    for (int i = 0; i < 8; i++) acc[i] = 0.f;
#pragma unroll 4
    for (int d = 0; d < D; d += 4) {
        float c0 = g_C[(d + 0) * D + t];
        float c1 = g_C[(d + 1) * D + t];
        float c2 = g_C[(d + 2) * D + t];
        float c3 = g_C[(d + 3) * D + t];
#pragma unroll
        for (int i = 0; i < 8; i++) {
            float4 vv = *(const float4*)&v[r0 + i][d];
            acc[i] = fmaf(c0, vv.x, acc[i]);
            acc[i] = fmaf(c1, vv.y, acc[i]);
            acc[i] = fmaf(c2, vv.z, acc[i]);
            acc[i] = fmaf(c3, vv.w, acc[i]);
        }
    }
#pragma unroll
    for (int i = 0; i < 8; i++) ys[r0 + i][t] = acc[i];
    __syncthreads();

    float qacc[8];
#pragma unroll
    for (int i = 0; i < 8; i++) qacc[i] = 0.f;
#pragma unroll 4
    for (int j = 0; j < D; j += 4) {
        float q0 = Q[(j + 0) * D + t];
        float q1 = Q[(j + 1) * D + t];
        float q2 = Q[(j + 2) * D + t];
        float q3 = Q[(j + 3) * D + t];
#pragma unroll
        for (int i = 0; i < 8; i++) {
            float4 yy = *(const float4*)&ys[r0 + i][j];
            qacc[i] = fmaf(q0, yy.x, qacc[i]);
            qacc[i] = fmaf(q1, yy.y, qacc[i]);
            qacc[i] = fmaf(q2, yy.z, qacc[i]);
            qacc[i] = fmaf(q3, yy.w, qacc[i]);
        }
    }
#pragma unroll
    for (int i = 0; i < 8; i++) {
        float p = acc[i] * qacc[i];
#pragma unroll
        for (int o = 16; o > 0; o >>= 1) p += __shfl_xor_sync(0xffffffffu, p, o);
        if (lane == 0) red[r0 + i][w] = p;
    }
    __syncthreads();
    if (t < 8) {
        int row = r0 + t;
        float h = red[row][0] + red[row][1] + red[row][2] + red[row][3];
        if (which == 0) g_h1[n0 + row] = h;
        else            g_h2[n0 + row] = h;
    }

    __half* dst = which ? g_At : g_Ae;
    float f = which ? 1.f : 2.f * lam[t];
#pragma unroll
    for (int i = 0; i < 8; i++) {
        float val = ys[r0 + i][t] * f;
        dst[(size_t)(n0 + r0 + i) * KT + t] = __float2half_rn(val);
    }
}

// ---------------------------------------------------------------------------
// HMMA GEMM: 128(M) x 128(N) tile per CTA, 256 threads, 8 warps (2x4),
// 2 CTAs/SM. K=128 in smem. Register double-buffered fragments.
// ---------------------------------------------------------------------------
#define GEMM_SMEM (2 * 128 * LDS_STRIDE * 2)   // 69632 bytes

__global__ __launch_bounds__(256, 2)
void gemm_hmma(float* __restrict__ out) {
    extern __shared__ char sm[];
    uint32_t sA = smem_u32(sm);
    uint32_t sB = sA + 128 * LDS_STRIDE * 2;

    int tid = threadIdx.x;
    int lane = tid & 31, wid = tid >> 5;
    int bm0 = blockIdx.y * 128;
    int bn0 = blockIdx.x * 128;

    const char* gA = (const char*)(g_Ae + (size_t)bm0 * KT);
    const char* gB = (const char*)(g_At + (size_t)bn0 * KT);

    // load BOTH FULL tiles (2 x 128 rows x 256 B) = 4096 16B chunks
#pragma unroll
    for (int u = 0; u < 16; u++) {
        int c = u * 256 + tid;           // 0..4095
        int tile = c >> 11;              // 0: A, 1: B
        int row = (c >> 4) & 127;
        int cc = c & 15;                 // 16 chunks x 16B = 256 B per row
        const char* gsrc = (tile ? gB : gA) + row * (KT * 2) + cc * 16;
        uint32_t sdst = (tile ? sB : sA) +
                        (uint32_t)(row * LDS_STRIDE * 2 + cc * 16);
        cp_async16(sdst, gsrc);
    }
    CP_COMMIT();

    int m0 = (wid >> 2) * 64;      // 2 m-groups
    int n0 = (wid & 3) * 32;       // 4 n-groups

    // fragment base addresses (kstep 0); each kstep advances +32 bytes
    int rowA = lane & 15;
    int kselA = (lane >> 4) << 3;
    uint32_t adA[4];
#pragma unroll
    for (int mi = 0; mi < 4; mi++)
        adA[mi] = sA + (uint32_t)((m0 + mi * 16 + rowA) * LDS_STRIDE + kselA) * 2u;
    int nrow = ((lane >> 4) & 1) * 8 + (lane & 7);
    int kselB = ((lane >> 3) & 1) * 8;
    uint32_t adB[2];
#pragma unroll
    for (int j = 0; j < 2; j++)
        adB[j] = sB + (uint32_t)((n0 + j * 16 + nrow) * LDS_STRIDE + kselB) * 2u;

    float acc[4][4][4];
#pragma unroll
    for (int mi = 0; mi < 4; mi++)
#pragma unroll
        for (int nj = 0; nj < 4; nj++)
#pragma unroll
            for (int e = 0; e < 4; e++) acc[mi][nj][e] = 0.f;

    asm volatile("cp.async.wait_group 0;" ::: "memory");
    __syncthreads();

    uint32_t a[2][4][4];
    uint32_t bb[2][2][4];

    // preload kstep 0 into buffer 0
#pragma unroll
    for (int mi = 0; mi < 4; mi++) ldsm_x4(a[0][mi], adA[mi]);
#pragma unroll
    for (int j = 0; j < 2; j++) ldsm_x4(bb[0][j], adB[j]);

#pragma unroll
    for (int k = 0; k < 8; k++) {
        int cur = k & 1, nxt = cur ^ 1;
        if (k < 7) {
            uint32_t off = (uint32_t)(k + 1) * 32u;
#pragma unroll
            for (int mi = 0; mi < 4; mi++) ldsm_x4(a[nxt][mi], adA[mi] + off);
#pragma unroll
            for (int j = 0; j < 2; j++) ldsm_x4(bb[nxt][j], adB[j] + off);
        }
#pragma unroll
        for (int mi = 0; mi < 4; mi++) {
#pragma unroll
            for (int j = 0; j < 2; j++) {
                mma16816(acc[mi][2 * j],     a[cur][mi], bb[cur][j][0], bb[cur][j][1]);
                mma16816(acc[mi][2 * j + 1], a[cur][mi], bb[cur][j][2], bb[cur][j][3]);
            }
        }
    }

    // epilogue: + h1[row] + h2[col]
    int r0base = bm0 + m0 + (lane >> 2);
    int cbase = bn0 + n0 + 2 * (lane & 3);

    float h2v[4][2];
#pragma unroll
    for (int nj = 0; nj < 4; nj++) {
        h2v[nj][0] = g_h2[cbase + nj * 8];
        h2v[nj][1] = g_h2[cbase + nj * 8 + 1];
    }

#pragma unroll
    for (int mi = 0; mi < 4; mi++) {
        int gr0 = r0base + mi * 16;
        int gr1 = gr0 + 8;
        float h10 = g_h1[gr0];
        float h11 = g_h1[gr1];
#pragma unroll
        for (int nj = 0; nj < 4; nj++) {
            int gc = cbase + nj * 8;
            float2 v0 = make_float2(acc[mi][nj][0] + h10 + h2v[nj][0],
                                    acc[mi][nj][1] + h10 + h2v[nj][1]);
            float2 v1 = make_float2(acc[mi][nj][2] + h11 + h2v[nj][0],
                                    acc[mi][nj][3] + h11 + h2v[nj][1]);
            *(float2*)(out + (size_t)gr0 * NT + gc) = v0;
            *(float2*)(out + (size_t)gr1 * NT + gc) = v1;
        }
    }
}

// ---------------------------------------------------------------------------
extern "C" void kernel_launch(void* const* d_in, const int* in_sizes, int n_in,
                              void* d_out, int out_size) {
    const float* x_enroll = (const float*)d_in[0];
    const float* x_test   = (const float*)d_in[1];
    const float* W        = (const float*)d_in[2];
    const float* miu      = (const float*)d_in[3];
    const float* lam      = (const float*)d_in[4];
    const float* U_k      = (const float*)d_in[5];
    const float* Q_hat    = (const float*)d_in[6];
    float* out = (float*)d_out;

    build_C_kernel<<<128, 128>>>(W, U_k);
    project_kernel<<<dim3(NE / RPB, 2), 256>>>(x_enroll, x_test, miu, Q_hat, lam);

    cudaFuncSetAttribute(gemm_hmma, cudaFuncAttributeMaxDynamicSharedMemorySize,
                         GEMM_SMEM);
    dim3 grid(NT / 128, NE / 128);
    gemm_hmma<<<grid, 256, GEMM_SMEM>>>(out);
}